// round 10
// baseline (speedup 1.0000x reference)
#include <cuda_runtime.h>
#include <cuda_bf16.h>
#include <math.h>

#define NMAX 100000
#define EMAX 1600000
#define F1   128   // hidden
#define FIN  256

// ---------------- scratch (static __device__ arrays) --------------------------
__device__ float g_T1[(size_t)NMAX * F1];
__device__ float g_H [(size_t)NMAX * F1];
__device__ float g_AH[(size_t)NMAX * F1];
__device__ float g_dinv[NMAX];
__device__ int   g_deg [NMAX];
__device__ int   g_rowstart[NMAX];
__device__ int   g_cur[NMAX];
__device__ int   g_csr[EMAX];
__device__ int   g_blocksums[512];
__device__ int   g_blockoff[512];

// ---------------- packed f32x2 fma -------------------------------------------
__device__ __forceinline__ unsigned long long ffma2(unsigned long long a,
                                                    unsigned long long b,
                                                    unsigned long long c) {
    unsigned long long d;
    asm("fma.rn.f32x2 %0, %1, %2, %3;" : "=l"(d) : "l"(a), "l"(b), "l"(c));
    return d;
}
__device__ __forceinline__ unsigned long long dup_f32(float a) {
    unsigned long long d;
    asm("mov.b64 %0, {%1, %1};" : "=l"(d) : "f"(a));
    return d;
}

// ---------------- degree ------------------------------------------------------
__global__ void zero_deg_kernel(int* __restrict__ deg, int n) {
    int i = blockIdx.x * blockDim.x + threadIdx.x;
    if (i < n) deg[i] = 0;
}

__global__ void deg_kernel(const int* __restrict__ ei, int E, int Nn, int* __restrict__ deg) {
    int e = blockIdx.x * blockDim.x + threadIdx.x;
    if (e < E) {
        int c = ei[E + e];
        if ((unsigned)c < (unsigned)Nn) atomicAdd(&deg[c], 1);
    }
}

__global__ void dinv_kernel(const int* __restrict__ deg, float* __restrict__ dinv, int n) {
    int i = blockIdx.x * blockDim.x + threadIdx.x;
    if (i < n) dinv[i] = rsqrtf((float)(deg[i] + 1));
}

// ---------------- prefix-sum (3 kernels) for CSR row starts -------------------
__global__ void scan1_kernel(const int* __restrict__ deg, int n,
                             int* __restrict__ row_start, int* __restrict__ blockSums) {
    __shared__ int s[256];
    int tid = threadIdx.x;
    int i = blockIdx.x * 256 + tid;
    int v = (i < n) ? deg[i] : 0;
    s[tid] = v; __syncthreads();
    #pragma unroll
    for (int off = 1; off < 256; off <<= 1) {
        int t = (tid >= off) ? s[tid - off] : 0;
        __syncthreads();
        s[tid] += t;
        __syncthreads();
    }
    if (i < n) row_start[i] = s[tid] - v;
    if (tid == 255) blockSums[blockIdx.x] = s[255];
}

__global__ void scan2_kernel(const int* __restrict__ blockSums, int nb,
                             int* __restrict__ blockOff) {
    __shared__ int s[512];
    int tid = threadIdx.x;
    int v = (tid < nb) ? blockSums[tid] : 0;
    s[tid] = v; __syncthreads();
    #pragma unroll
    for (int off = 1; off < 512; off <<= 1) {
        int t = (tid >= off) ? s[tid - off] : 0;
        __syncthreads();
        s[tid] += t;
        __syncthreads();
    }
    if (tid < nb) blockOff[tid] = s[tid] - v;
}

__global__ void scan3_kernel(int* __restrict__ row_start, const int* __restrict__ blockOff,
                             int n, int* __restrict__ cur) {
    int i = blockIdx.x * 256 + threadIdx.x;
    if (i < n) {
        int rs = row_start[i] + blockOff[blockIdx.x];
        row_start[i] = rs;
        cur[i] = rs;
    }
}

__global__ void fill_kernel(const int* __restrict__ ei, int E, int Nn,
                            int* __restrict__ cur, int* __restrict__ csr) {
    int e = blockIdx.x * blockDim.x + threadIdx.x;
    if (e < E) {
        int r = ei[e];
        int c = ei[E + e];
        if ((unsigned)r < (unsigned)Nn && (unsigned)c < (unsigned)Nn) {
            int pos = atomicAdd(&cur[c], 1);
            csr[pos] = r;
        }
    }
}

// ---------------- CSR gather aggregation: out[c] = feat[c] + sum_nbr feat[r] --
__global__ void agg_csr_kernel(const int* __restrict__ row_start,
                               const int* __restrict__ deg,
                               const int* __restrict__ csr,
                               const float* __restrict__ feat,
                               float* __restrict__ out, int Nn) {
    int node = (blockIdx.x * blockDim.x + threadIdx.x) >> 5;
    int lane = threadIdx.x & 31;
    if (node >= Nn) return;
    int start = row_start[node];
    int len   = deg[node];
    const float4* f4 = (const float4*)feat;
    float4 acc = f4[(size_t)node * 32 + lane];
    int j = 0;
    for (; j + 4 <= len; j += 4) {
        int r0 = __ldg(csr + start + j + 0);
        int r1 = __ldg(csr + start + j + 1);
        int r2 = __ldg(csr + start + j + 2);
        int r3 = __ldg(csr + start + j + 3);
        float4 a = f4[(size_t)r0 * 32 + lane];
        float4 b = f4[(size_t)r1 * 32 + lane];
        float4 c = f4[(size_t)r2 * 32 + lane];
        float4 d = f4[(size_t)r3 * 32 + lane];
        acc.x += (a.x + b.x) + (c.x + d.x);
        acc.y += (a.y + b.y) + (c.y + d.y);
        acc.z += (a.z + b.z) + (c.z + d.z);
        acc.w += (a.w + b.w) + (c.w + d.w);
    }
    for (; j < len; j++) {
        int r = __ldg(csr + start + j);
        float4 a = f4[(size_t)r * 32 + lane];
        acc.x += a.x; acc.y += a.y; acc.z += a.z; acc.w += a.w;
    }
    ((float4*)out)[(size_t)node * 32 + lane] = acc;
}

// ------- Hs = relu(Hraw * dinv[node] + b1) * dinv[node] -----------------------
__global__ void relu_scale_kernel(const float* __restrict__ Hraw, float* __restrict__ Hs,
                                  const float* __restrict__ dinv,
                                  const float* __restrict__ b1, int n) {
    int idx = blockIdx.x * blockDim.x + threadIdx.x;
    if (idx >= n * (F1 / 4)) return;
    int node = idx >> 5;
    int f4   = idx & 31;
    float w = dinv[node];
    float4 a = ((const float4*)Hraw)[idx];
    float4 b = ((const float4*)b1)[f4];
    float4 o;
    o.x = fmaxf(fmaf(a.x, w, b.x), 0.f) * w;
    o.y = fmaxf(fmaf(a.y, w, b.y), 0.f) * w;
    o.z = fmaxf(fmaf(a.z, w, b.z), 0.f) * w;
    o.w = fmaxf(fmaf(a.w, w, b.w), 0.f) * w;
    ((float4*)Hs)[idx] = o;
}

// ---------------- tiled fp32 GEMM (FFMA2): C = (A @ B) * rowscale[m] ----------
template<int BM, int BN, int BK, int TM, int TN>
__global__ void sgemm_oscale_kernel(const float* __restrict__ A, const float* __restrict__ B,
                                    const float* __restrict__ rowscale,
                                    float* __restrict__ C, int M, int N, int K) {
    constexpr int THREADS = (BM / TM) * (BN / TN);
    __shared__ float As[BK][BM + 4];
    __shared__ __align__(16) float Bs[BK][BN];
    const int tid  = threadIdx.x;
    const int brow = blockIdx.y * BM;
    const int bcol = blockIdx.x * BN;
    const int tr = (tid / (BN / TN)) * TM;
    const int tc = (tid % (BN / TN)) * TN;
    unsigned long long acc2[TM][TN / 2] = {};   // f32x2 pairs along N

    constexpr int A_F4 = BM * BK / 4;
    constexpr int B_F4 = BK * BN / 4;

    for (int k0 = 0; k0 < K; k0 += BK) {
        #pragma unroll
        for (int i = tid; i < A_F4; i += THREADS) {
            int r  = i / (BK / 4);
            int kq = i % (BK / 4);
            float4 v = make_float4(0.f, 0.f, 0.f, 0.f);
            int gr = brow + r;
            if (gr < M) v = *(const float4*)(A + (size_t)gr * K + k0 + kq * 4);
            As[kq * 4 + 0][r] = v.x;
            As[kq * 4 + 1][r] = v.y;
            As[kq * 4 + 2][r] = v.z;
            As[kq * 4 + 3][r] = v.w;
        }
        #pragma unroll
        for (int i = tid; i < B_F4; i += THREADS) {
            int kk = i / (BN / 4);
            int c4 = i % (BN / 4);
            *(float4*)&Bs[kk][c4 * 4] =
                *(const float4*)(B + (size_t)(k0 + kk) * N + bcol + c4 * 4);
        }
        __syncthreads();
        #pragma unroll
        for (int kk = 0; kk < BK; kk++) {
            float ra[TM];
            unsigned long long rb2[TN / 2];
            #pragma unroll
            for (int i = 0; i < TM; i++) ra[i] = As[kk][tr + i];
            #pragma unroll
            for (int j = 0; j < TN / 2; j++)
                rb2[j] = *(const unsigned long long*)&Bs[kk][tc + j * 2];
            #pragma unroll
            for (int i = 0; i < TM; i++) {
                unsigned long long ad = dup_f32(ra[i]);
                #pragma unroll
                for (int j = 0; j < TN / 2; j++)
                    acc2[i][j] = ffma2(ad, rb2[j], acc2[i][j]);
            }
        }
        __syncthreads();
    }

    #pragma unroll
    for (int i = 0; i < TM; i++) {
        int gr = brow + tr + i;
        if (gr >= M) continue;
        float w = rowscale[gr];
        #pragma unroll
        for (int j = 0; j < TN; j += 4) {
            float2 p0 = *(float2*)&acc2[i][j / 2];
            float2 p1 = *(float2*)&acc2[i][j / 2 + 1];
            float4 v;
            v.x = p0.x * w; v.y = p0.y * w;
            v.z = p1.x * w; v.w = p1.y * w;
            *(float4*)(C + (size_t)gr * N + bcol + tc + j) = v;
        }
    }
}

// --------- fused tail GEMM (FFMA2): [mu | lv] = (A*rowscale) @ [Wmu|Wlv]+bias -
template<int BM, int BK, int TM, int TN>
__global__ void tail_gemm_kernel(const float* __restrict__ A,
                                 const float* __restrict__ rowscale,
                                 const float* __restrict__ Wmu, const float* __restrict__ bmu,
                                 const float* __restrict__ Wlv, const float* __restrict__ blv,
                                 float* __restrict__ out, int M, int K) {
    constexpr int BN = 128;
    constexpr int THREADS = (BM / TM) * (BN / TN);
    __shared__ float As[BK][BM + 4];
    __shared__ __align__(16) float Bs[BK][BN];
    const int tid  = threadIdx.x;
    const int brow = blockIdx.y * BM;
    const int tr = (tid / (BN / TN)) * TM;
    const int tc = (tid % (BN / TN)) * TN;
    unsigned long long acc2[TM][TN / 2] = {};

    constexpr int A_F4 = BM * BK / 4;
    constexpr int B_F4 = BK * BN / 4;

    for (int k0 = 0; k0 < K; k0 += BK) {
        #pragma unroll
        for (int i = tid; i < A_F4; i += THREADS) {
            int r  = i / (BK / 4);
            int kq = i % (BK / 4);
            float4 v = make_float4(0.f, 0.f, 0.f, 0.f);
            int gr = brow + r;
            if (gr < M) {
                v = *(const float4*)(A + (size_t)gr * K + k0 + kq * 4);
                float w = rowscale[gr];
                v.x *= w; v.y *= w; v.z *= w; v.w *= w;
            }
            As[kq * 4 + 0][r] = v.x;
            As[kq * 4 + 1][r] = v.y;
            As[kq * 4 + 2][r] = v.z;
            As[kq * 4 + 3][r] = v.w;
        }
        #pragma unroll
        for (int i = tid; i < B_F4; i += THREADS) {
            int kk = i / (BN / 4);
            int c4 = i % (BN / 4);          // c4<16 -> mu, else lv
            const float* src = (c4 < 16) ? (Wmu + (size_t)(k0 + kk) * 64 + c4 * 4)
                                         : (Wlv + (size_t)(k0 + kk) * 64 + (c4 - 16) * 4);
            *(float4*)&Bs[kk][c4 * 4] = *(const float4*)src;
        }
        __syncthreads();
        #pragma unroll
        for (int kk = 0; kk < BK; kk++) {
            float ra[TM];
            unsigned long long rb2[TN / 2];
            #pragma unroll
            for (int i = 0; i < TM; i++) ra[i] = As[kk][tr + i];
            #pragma unroll
            for (int j = 0; j < TN / 2; j++)
                rb2[j] = *(const unsigned long long*)&Bs[kk][tc + j * 2];
            #pragma unroll
            for (int i = 0; i < TM; i++) {
                unsigned long long ad = dup_f32(ra[i]);
                #pragma unroll
                for (int j = 0; j < TN / 2; j++)
                    acc2[i][j] = ffma2(ad, rb2[j], acc2[i][j]);
            }
        }
        __syncthreads();
    }

    #pragma unroll
    for (int i = 0; i < TM; i++) {
        int gr = brow + tr + i;
        if (gr >= M) continue;
        #pragma unroll
        for (int j = 0; j < TN; j += 4) {
            int col = tc + j;
            int lcol = (col < 64) ? col : col - 64;
            const float* bias = (col < 64) ? bmu : blv;
            float* base = (col < 64) ? out : out + (size_t)M * 64;
            float2 p0 = *(float2*)&acc2[i][j / 2];
            float2 p1 = *(float2*)&acc2[i][j / 2 + 1];
            float4 v;
            v.x = p0.x + bias[lcol + 0];
            v.y = p0.y + bias[lcol + 1];
            v.z = p1.x + bias[lcol + 2];
            v.w = p1.y + bias[lcol + 3];
            *(float4*)(base + (size_t)gr * 64 + lcol) = v;
        }
    }
}

// ---------------- launch ------------------------------------------------------
extern "C" void kernel_launch(void* const* d_in, const int* in_sizes, int n_in,
                              void* d_out, int out_size) {
    const float* X   = (const float*)d_in[0];
    const int*   ei  = (const int*)d_in[1];
    const float* W1  = (const float*)d_in[2];
    const float* b1  = (const float*)d_in[3];
    const float* Wmu = (const float*)d_in[4];
    const float* bmu = (const float*)d_in[5];
    const float* Wlv = (const float*)d_in[6];
    const float* blv = (const float*)d_in[7];
    const int Nn = in_sizes[0] / FIN;       // 100000
    const int E  = in_sizes[1] / 2;         // 1600000
    float* out = (float*)d_out;

    float *T1, *H, *AH, *dinv;
    int *deg, *row_start, *cur, *csr, *bsums, *boff;
    cudaGetSymbolAddress((void**)&T1,       g_T1);
    cudaGetSymbolAddress((void**)&H,        g_H);
    cudaGetSymbolAddress((void**)&AH,       g_AH);
    cudaGetSymbolAddress((void**)&dinv,     g_dinv);
    cudaGetSymbolAddress((void**)&deg,      g_deg);
    cudaGetSymbolAddress((void**)&row_start,g_rowstart);
    cudaGetSymbolAddress((void**)&cur,      g_cur);
    cudaGetSymbolAddress((void**)&csr,      g_csr);
    cudaGetSymbolAddress((void**)&bsums,    g_blocksums);
    cudaGetSymbolAddress((void**)&boff,     g_blockoff);

    const int n4 = Nn * (F1 / 4);
    const int nblk256 = (Nn + 255) / 256;   // 391

    // degrees + dinv
    zero_deg_kernel<<<nblk256, 256>>>(deg, Nn);
    deg_kernel<<<(E + 255) / 256, 256>>>(ei, E, Nn, deg);
    dinv_kernel<<<nblk256, 256>>>(deg, dinv, Nn);

    // CSR build
    scan1_kernel<<<nblk256, 256>>>(deg, Nn, row_start, bsums);
    scan2_kernel<<<1, 512>>>(bsums, nblk256, boff);
    scan3_kernel<<<nblk256, 256>>>(row_start, boff, Nn, cur);
    fill_kernel<<<(E + 255) / 256, 256>>>(ei, E, Nn, cur, csr);

    // T1s = (X @ W1) * dinv[row]
    {
        dim3 grid(1, (Nn + 127) / 128);
        sgemm_oscale_kernel<128, 128, 32, 8, 8><<<grid, 256>>>(X, W1, dinv, T1, Nn, F1, FIN);
    }

    // layer 1 aggregation (gather)
    {
        int blocks = (Nn * 32 + 255) / 256;
        agg_csr_kernel<<<blocks, 256>>>(row_start, deg, csr, T1, H, Nn);
    }

    // Hs = relu(Hraw * dinv + b1) * dinv
    relu_scale_kernel<<<(n4 + 255) / 256, 256>>>(H, AH, dinv, b1, Nn);

    // layer 2 aggregation (gather)
    {
        int blocks = (Nn * 32 + 255) / 256;
        agg_csr_kernel<<<blocks, 256>>>(row_start, deg, csr, AH, H, Nn);
    }

    // [mu | lv] = (AHraw * dinv[row]) @ [Wmu | Wlv] + bias
    {
        dim3 grid(1, (Nn + 127) / 128);
        tail_gemm_kernel<128, 32, 8, 8><<<grid, 256>>>(H, dinv, Wmu, bmu, Wlv, blv, out, Nn, F1);
    }
}

// round 11
// speedup vs baseline: 1.3231x; 1.3231x over previous
#include <cuda_runtime.h>
#include <cuda_bf16.h>
#include <math.h>

#define NMAX 100000
#define EMAX 1600000
#define F1   128   // hidden
#define FIN  256

// ---------------- scratch (static __device__ arrays) --------------------------
__device__ float g_T1[(size_t)NMAX * F1];
__device__ float g_H [(size_t)NMAX * F1];
__device__ float g_AH[(size_t)NMAX * F1];
__device__ float g_dinv[NMAX];
__device__ int   g_deg [NMAX];
__device__ int   g_rowstart[NMAX];
__device__ int   g_cur[NMAX];
__device__ int   g_csr[EMAX];
__device__ int   g_blocksums[512];
__device__ int   g_blockoff[512];

// ---------------- degree ------------------------------------------------------
__global__ void zero_deg_kernel(int* __restrict__ deg, int n) {
    int i = blockIdx.x * blockDim.x + threadIdx.x;
    if (i < n) deg[i] = 0;
}

__global__ void deg_kernel(const int* __restrict__ ei, int E, int Nn, int* __restrict__ deg) {
    int e = blockIdx.x * blockDim.x + threadIdx.x;
    if (e < E) {
        int c = ei[E + e];
        if ((unsigned)c < (unsigned)Nn) atomicAdd(&deg[c], 1);
    }
}

__global__ void dinv_kernel(const int* __restrict__ deg, float* __restrict__ dinv, int n) {
    int i = blockIdx.x * blockDim.x + threadIdx.x;
    if (i < n) dinv[i] = rsqrtf((float)(deg[i] + 1));
}

// ---------------- prefix-sum (3 kernels) for CSR row starts -------------------
__global__ void scan1_kernel(const int* __restrict__ deg, int n,
                             int* __restrict__ row_start, int* __restrict__ blockSums) {
    __shared__ int s[256];
    int tid = threadIdx.x;
    int i = blockIdx.x * 256 + tid;
    int v = (i < n) ? deg[i] : 0;
    s[tid] = v; __syncthreads();
    #pragma unroll
    for (int off = 1; off < 256; off <<= 1) {
        int t = (tid >= off) ? s[tid - off] : 0;
        __syncthreads();
        s[tid] += t;
        __syncthreads();
    }
    if (i < n) row_start[i] = s[tid] - v;
    if (tid == 255) blockSums[blockIdx.x] = s[255];
}

__global__ void scan2_kernel(const int* __restrict__ blockSums, int nb,
                             int* __restrict__ blockOff) {
    __shared__ int s[512];
    int tid = threadIdx.x;
    int v = (tid < nb) ? blockSums[tid] : 0;
    s[tid] = v; __syncthreads();
    #pragma unroll
    for (int off = 1; off < 512; off <<= 1) {
        int t = (tid >= off) ? s[tid - off] : 0;
        __syncthreads();
        s[tid] += t;
        __syncthreads();
    }
    if (tid < nb) blockOff[tid] = s[tid] - v;
}

__global__ void scan3_kernel(int* __restrict__ row_start, const int* __restrict__ blockOff,
                             int n, int* __restrict__ cur) {
    int i = blockIdx.x * 256 + threadIdx.x;
    if (i < n) {
        int rs = row_start[i] + blockOff[blockIdx.x];
        row_start[i] = rs;
        cur[i] = rs;
    }
}

__global__ void fill_kernel(const int* __restrict__ ei, int E, int Nn,
                            int* __restrict__ cur, int* __restrict__ csr) {
    int e = blockIdx.x * blockDim.x + threadIdx.x;
    if (e < E) {
        int r = ei[e];
        int c = ei[E + e];
        if ((unsigned)r < (unsigned)Nn && (unsigned)c < (unsigned)Nn) {
            int pos = atomicAdd(&cur[c], 1);
            csr[pos] = r;
        }
    }
}

// ---------------- CSR gather aggregation -------------------------------------
// acc = feat[c] + sum_nbr feat[r]; optional fused epilogue:
//   RELU=false: out = acc
//   RELU=true : out = relu(acc * dinv[c] + b1) * dinv[c]
template<bool RELU>
__global__ void agg_csr_kernel(const int* __restrict__ row_start,
                               const int* __restrict__ deg,
                               const int* __restrict__ csr,
                               const float* __restrict__ feat,
                               const float* __restrict__ dinv,
                               const float* __restrict__ b1,
                               float* __restrict__ out, int Nn) {
    int node = (blockIdx.x * blockDim.x + threadIdx.x) >> 5;
    int lane = threadIdx.x & 31;
    if (node >= Nn) return;
    int start = row_start[node];
    int len   = deg[node];
    const float4* f4 = (const float4*)feat;
    float4 acc = f4[(size_t)node * 32 + lane];
    int j = 0;
    for (; j + 4 <= len; j += 4) {
        int r0 = __ldg(csr + start + j + 0);
        int r1 = __ldg(csr + start + j + 1);
        int r2 = __ldg(csr + start + j + 2);
        int r3 = __ldg(csr + start + j + 3);
        float4 a = f4[(size_t)r0 * 32 + lane];
        float4 b = f4[(size_t)r1 * 32 + lane];
        float4 c = f4[(size_t)r2 * 32 + lane];
        float4 d = f4[(size_t)r3 * 32 + lane];
        acc.x += (a.x + b.x) + (c.x + d.x);
        acc.y += (a.y + b.y) + (c.y + d.y);
        acc.z += (a.z + b.z) + (c.z + d.z);
        acc.w += (a.w + b.w) + (c.w + d.w);
    }
    for (; j < len; j++) {
        int r = __ldg(csr + start + j);
        float4 a = f4[(size_t)r * 32 + lane];
        acc.x += a.x; acc.y += a.y; acc.z += a.z; acc.w += a.w;
    }
    if (RELU) {
        float w = dinv[node];
        float4 b = ((const float4*)b1)[lane];
        acc.x = fmaxf(fmaf(acc.x, w, b.x), 0.f) * w;
        acc.y = fmaxf(fmaf(acc.y, w, b.y), 0.f) * w;
        acc.z = fmaxf(fmaf(acc.z, w, b.z), 0.f) * w;
        acc.w = fmaxf(fmaf(acc.w, w, b.w), 0.f) * w;
    }
    ((float4*)out)[(size_t)node * 32 + lane] = acc;
}

// ---------------- tiled fp32 GEMM: C[M,N] = (A[M,K] @ B[K,N]) * rowscale[m] ---
template<int BM, int BN, int BK, int TM, int TN>
__global__ void sgemm_oscale_kernel(const float* __restrict__ A, const float* __restrict__ B,
                                    const float* __restrict__ rowscale,
                                    float* __restrict__ C, int M, int N, int K) {
    constexpr int THREADS = (BM / TM) * (BN / TN);
    __shared__ float As[BK][BM + 4];
    __shared__ float Bs[BK][BN];
    const int tid  = threadIdx.x;
    const int brow = blockIdx.y * BM;
    const int bcol = blockIdx.x * BN;
    const int tr = (tid / (BN / TN)) * TM;
    const int tc = (tid % (BN / TN)) * TN;
    float acc[TM][TN] = {};

    constexpr int A_F4 = BM * BK / 4;
    constexpr int B_F4 = BK * BN / 4;

    for (int k0 = 0; k0 < K; k0 += BK) {
        #pragma unroll
        for (int i = tid; i < A_F4; i += THREADS) {
            int r  = i / (BK / 4);
            int kq = i % (BK / 4);
            float4 v = make_float4(0.f, 0.f, 0.f, 0.f);
            int gr = brow + r;
            if (gr < M) v = *(const float4*)(A + (size_t)gr * K + k0 + kq * 4);
            As[kq * 4 + 0][r] = v.x;
            As[kq * 4 + 1][r] = v.y;
            As[kq * 4 + 2][r] = v.z;
            As[kq * 4 + 3][r] = v.w;
        }
        #pragma unroll
        for (int i = tid; i < B_F4; i += THREADS) {
            int kk = i / (BN / 4);
            int c4 = i % (BN / 4);
            *(float4*)&Bs[kk][c4 * 4] =
                *(const float4*)(B + (size_t)(k0 + kk) * N + bcol + c4 * 4);
        }
        __syncthreads();
        #pragma unroll
        for (int kk = 0; kk < BK; kk++) {
            float ra[TM], rb[TN];
            #pragma unroll
            for (int i = 0; i < TM; i++) ra[i] = As[kk][tr + i];
            #pragma unroll
            for (int j = 0; j < TN; j++) rb[j] = Bs[kk][tc + j];
            #pragma unroll
            for (int i = 0; i < TM; i++)
                #pragma unroll
                for (int j = 0; j < TN; j++)
                    acc[i][j] = fmaf(ra[i], rb[j], acc[i][j]);
        }
        __syncthreads();
    }

    #pragma unroll
    for (int i = 0; i < TM; i++) {
        int gr = brow + tr + i;
        if (gr >= M) continue;
        float w = rowscale[gr];
        #pragma unroll
        for (int j = 0; j < TN; j += 4) {
            float4 v;
            v.x = acc[i][j + 0] * w; v.y = acc[i][j + 1] * w;
            v.z = acc[i][j + 2] * w; v.w = acc[i][j + 3] * w;
            *(float4*)(C + (size_t)gr * N + bcol + tc + j) = v;
        }
    }
}

// --------- fused tail GEMM: [mu | lv] = (A*rowscale) @ [Wmu | Wlv] + bias -----
template<int BM, int BK, int TM, int TN>
__global__ void tail_gemm_kernel(const float* __restrict__ A,
                                 const float* __restrict__ rowscale,
                                 const float* __restrict__ Wmu, const float* __restrict__ bmu,
                                 const float* __restrict__ Wlv, const float* __restrict__ blv,
                                 float* __restrict__ out, int M, int K) {
    constexpr int BN = 128;
    constexpr int THREADS = (BM / TM) * (BN / TN);
    __shared__ float As[BK][BM + 4];
    __shared__ float Bs[BK][BN];
    const int tid  = threadIdx.x;
    const int brow = blockIdx.y * BM;
    const int tr = (tid / (BN / TN)) * TM;
    const int tc = (tid % (BN / TN)) * TN;
    float acc[TM][TN] = {};

    constexpr int A_F4 = BM * BK / 4;
    constexpr int B_F4 = BK * BN / 4;

    for (int k0 = 0; k0 < K; k0 += BK) {
        #pragma unroll
        for (int i = tid; i < A_F4; i += THREADS) {
            int r  = i / (BK / 4);
            int kq = i % (BK / 4);
            float4 v = make_float4(0.f, 0.f, 0.f, 0.f);
            int gr = brow + r;
            if (gr < M) {
                v = *(const float4*)(A + (size_t)gr * K + k0 + kq * 4);
                float w = rowscale[gr];
                v.x *= w; v.y *= w; v.z *= w; v.w *= w;
            }
            As[kq * 4 + 0][r] = v.x;
            As[kq * 4 + 1][r] = v.y;
            As[kq * 4 + 2][r] = v.z;
            As[kq * 4 + 3][r] = v.w;
        }
        #pragma unroll
        for (int i = tid; i < B_F4; i += THREADS) {
            int kk = i / (BN / 4);
            int c4 = i % (BN / 4);          // c4<16 -> mu, else lv
            const float* src = (c4 < 16) ? (Wmu + (size_t)(k0 + kk) * 64 + c4 * 4)
                                         : (Wlv + (size_t)(k0 + kk) * 64 + (c4 - 16) * 4);
            *(float4*)&Bs[kk][c4 * 4] = *(const float4*)src;
        }
        __syncthreads();
        #pragma unroll
        for (int kk = 0; kk < BK; kk++) {
            float ra[TM], rb[TN];
            #pragma unroll
            for (int i = 0; i < TM; i++) ra[i] = As[kk][tr + i];
            #pragma unroll
            for (int j = 0; j < TN; j++) rb[j] = Bs[kk][tc + j];
            #pragma unroll
            for (int i = 0; i < TM; i++)
                #pragma unroll
                for (int j = 0; j < TN; j++)
                    acc[i][j] = fmaf(ra[i], rb[j], acc[i][j]);
        }
        __syncthreads();
    }

    #pragma unroll
    for (int i = 0; i < TM; i++) {
        int gr = brow + tr + i;
        if (gr >= M) continue;
        #pragma unroll
        for (int j = 0; j < TN; j += 4) {
            int col = tc + j;
            int lcol = (col < 64) ? col : col - 64;
            const float* bias = (col < 64) ? bmu : blv;
            float* base = (col < 64) ? out : out + (size_t)M * 64;
            float4 v;
            v.x = acc[i][j + 0] + bias[lcol + 0];
            v.y = acc[i][j + 1] + bias[lcol + 1];
            v.z = acc[i][j + 2] + bias[lcol + 2];
            v.w = acc[i][j + 3] + bias[lcol + 3];
            *(float4*)(base + (size_t)gr * 64 + lcol) = v;
        }
    }
}

// ---------------- launch ------------------------------------------------------
extern "C" void kernel_launch(void* const* d_in, const int* in_sizes, int n_in,
                              void* d_out, int out_size) {
    const float* X   = (const float*)d_in[0];
    const int*   ei  = (const int*)d_in[1];
    const float* W1  = (const float*)d_in[2];
    const float* b1  = (const float*)d_in[3];
    const float* Wmu = (const float*)d_in[4];
    const float* bmu = (const float*)d_in[5];
    const float* Wlv = (const float*)d_in[6];
    const float* blv = (const float*)d_in[7];
    const int Nn = in_sizes[0] / FIN;       // 100000
    const int E  = in_sizes[1] / 2;         // 1600000
    float* out = (float*)d_out;

    float *T1, *H, *AH, *dinv;
    int *deg, *row_start, *cur, *csr, *bsums, *boff;
    cudaGetSymbolAddress((void**)&T1,       g_T1);
    cudaGetSymbolAddress((void**)&H,        g_H);
    cudaGetSymbolAddress((void**)&AH,       g_AH);
    cudaGetSymbolAddress((void**)&dinv,     g_dinv);
    cudaGetSymbolAddress((void**)&deg,      g_deg);
    cudaGetSymbolAddress((void**)&row_start,g_rowstart);
    cudaGetSymbolAddress((void**)&cur,      g_cur);
    cudaGetSymbolAddress((void**)&csr,      g_csr);
    cudaGetSymbolAddress((void**)&bsums,    g_blocksums);
    cudaGetSymbolAddress((void**)&boff,     g_blockoff);

    const int nblk256 = (Nn + 255) / 256;   // 391

    // degrees + dinv
    zero_deg_kernel<<<nblk256, 256>>>(deg, Nn);
    deg_kernel<<<(E + 255) / 256, 256>>>(ei, E, Nn, deg);
    dinv_kernel<<<nblk256, 256>>>(deg, dinv, Nn);

    // CSR build
    scan1_kernel<<<nblk256, 256>>>(deg, Nn, row_start, bsums);
    scan2_kernel<<<1, 512>>>(bsums, nblk256, boff);
    scan3_kernel<<<nblk256, 256>>>(row_start, boff, Nn, cur);
    fill_kernel<<<(E + 255) / 256, 256>>>(ei, E, Nn, cur, csr);

    // T1s = (X @ W1) * dinv[row]
    {
        dim3 grid(1, (Nn + 127) / 128);
        sgemm_oscale_kernel<128, 128, 32, 8, 8><<<grid, 256>>>(X, W1, dinv, T1, Nn, F1, FIN);
    }

    // layer 1 aggregation + fused relu/bias/scale: Hs = relu(agg*dinv + b1)*dinv
    {
        int blocks = (Nn * 32 + 255) / 256;
        agg_csr_kernel<true><<<blocks, 256>>>(row_start, deg, csr, T1, dinv, b1, AH, Nn);
    }

    // layer 2 aggregation (raw): AHraw[c] = Hs[c] + sum_r Hs[r]  -> into H
    {
        int blocks = (Nn * 32 + 255) / 256;
        agg_csr_kernel<false><<<blocks, 256>>>(row_start, deg, csr, AH, dinv, b1, H, Nn);
    }

    // [mu | lv] = (AHraw * dinv[row]) @ [Wmu | Wlv] + bias
    {
        dim3 grid(1, (Nn + 127) / 128);
        tail_gemm_kernel<128, 32, 8, 8><<<grid, 256>>>(H, dinv, Wmu, bmu, Wlv, blv, out, Nn, F1);
    }
}

// round 14
// speedup vs baseline: 1.3673x; 1.0334x over previous
#include <cuda_runtime.h>
#include <cuda_fp16.h>
#include <math.h>

#define NMAX 100000
#define EMAX 1600000
#define F1   128   // hidden
#define FIN  256

// ---------------- scratch (static __device__ arrays) --------------------------
__device__ __half g_T1h[(size_t)NMAX * F1];  // half T1s = (X@W1)*dinv
__device__ __half g_Hh [(size_t)NMAX * F1];  // half Hs  = relu(...)*dinv
__device__ float  g_H  [(size_t)NMAX * F1];  // fp32 AHraw (tail GEMM input)
__device__ float  g_dinv[NMAX];
__device__ int    g_deg [NMAX];
__device__ int    g_rowstart[NMAX];
__device__ int    g_cur[NMAX];
__device__ int    g_csr[EMAX];
__device__ int    g_blocksums[512];
__device__ int    g_blockoff[512];

// ---------------- degree ------------------------------------------------------
__global__ void zero_deg_kernel(int* __restrict__ deg, int n) {
    int i = blockIdx.x * blockDim.x + threadIdx.x;
    if (i < n) deg[i] = 0;
}

__global__ void deg_kernel(const int* __restrict__ ei, int E, int Nn, int* __restrict__ deg) {
    int e = blockIdx.x * blockDim.x + threadIdx.x;
    if (e < E) {
        int c = ei[E + e];
        if ((unsigned)c < (unsigned)Nn) atomicAdd(&deg[c], 1);
    }
}

__global__ void dinv_kernel(const int* __restrict__ deg, float* __restrict__ dinv, int n) {
    int i = blockIdx.x * blockDim.x + threadIdx.x;
    if (i < n) dinv[i] = rsqrtf((float)(deg[i] + 1));
}

// ---------------- prefix-sum (3 kernels) for CSR row starts -------------------
__global__ void scan1_kernel(const int* __restrict__ deg, int n,
                             int* __restrict__ row_start, int* __restrict__ blockSums) {
    __shared__ int s[256];
    int tid = threadIdx.x;
    int i = blockIdx.x * 256 + tid;
    int v = (i < n) ? deg[i] : 0;
    s[tid] = v; __syncthreads();
    #pragma unroll
    for (int off = 1; off < 256; off <<= 1) {
        int t = (tid >= off) ? s[tid - off] : 0;
        __syncthreads();
        s[tid] += t;
        __syncthreads();
    }
    if (i < n) row_start[i] = s[tid] - v;
    if (tid == 255) blockSums[blockIdx.x] = s[255];
}

__global__ void scan2_kernel(const int* __restrict__ blockSums, int nb,
                             int* __restrict__ blockOff) {
    __shared__ int s[512];
    int tid = threadIdx.x;
    int v = (tid < nb) ? blockSums[tid] : 0;
    s[tid] = v; __syncthreads();
    #pragma unroll
    for (int off = 1; off < 512; off <<= 1) {
        int t = (tid >= off) ? s[tid - off] : 0;
        __syncthreads();
        s[tid] += t;
        __syncthreads();
    }
    if (tid < nb) blockOff[tid] = s[tid] - v;
}

__global__ void scan3_kernel(int* __restrict__ row_start, const int* __restrict__ blockOff,
                             int n, int* __restrict__ cur) {
    int i = blockIdx.x * 256 + threadIdx.x;
    if (i < n) {
        int rs = row_start[i] + blockOff[blockIdx.x];
        row_start[i] = rs;
        cur[i] = rs;
    }
}

__global__ void fill_kernel(const int* __restrict__ ei, int E, int Nn,
                            int* __restrict__ cur, int* __restrict__ csr) {
    int e = blockIdx.x * blockDim.x + threadIdx.x;
    if (e < E) {
        int r = ei[e];
        int c = ei[E + e];
        if ((unsigned)r < (unsigned)Nn && (unsigned)c < (unsigned)Nn) {
            int pos = atomicAdd(&cur[c], 1);
            csr[pos] = r;
        }
    }
}

// ---------------- CSR gather aggregation over HALF feature tables -------------
// acc(fp32) = feat[c] + sum_nbr feat[r]   (feat is __half, row = 128 halves)
// RELU=true : write half2 Hs = relu(acc*dinv + b1)*dinv  to (half*)out
// RELU=false: write float4 acc to (float*)out
template<bool RELU>
__global__ void agg_half_kernel(const int* __restrict__ row_start,
                                const int* __restrict__ deg,
                                const int* __restrict__ csr,
                                const __half* __restrict__ feat,
                                const float* __restrict__ dinv,
                                const float* __restrict__ b1,
                                void* __restrict__ out, int Nn) {
    int node = (blockIdx.x * blockDim.x + threadIdx.x) >> 5;
    int lane = threadIdx.x & 31;
    if (node >= Nn) return;
    int start = row_start[node];
    int len   = deg[node];
    const uint2* f2 = (const uint2*)feat;   // 32 x uint2 (4 halves) per row
    uint2 u = __ldg(&f2[(size_t)node * 32 + lane]);
    float2 s0 = __half22float2(*(__half2*)&u.x);
    float2 s1 = __half22float2(*(__half2*)&u.y);
    float4 acc = make_float4(s0.x, s0.y, s1.x, s1.y);
    int j = 0;
    for (; j + 4 <= len; j += 4) {
        int r0 = __ldg(csr + start + j + 0);
        int r1 = __ldg(csr + start + j + 1);
        int r2 = __ldg(csr + start + j + 2);
        int r3 = __ldg(csr + start + j + 3);
        uint2 ua = __ldg(&f2[(size_t)r0 * 32 + lane]);
        uint2 ub = __ldg(&f2[(size_t)r1 * 32 + lane]);
        uint2 uc = __ldg(&f2[(size_t)r2 * 32 + lane]);
        uint2 ud = __ldg(&f2[(size_t)r3 * 32 + lane]);
        float2 a0 = __half22float2(*(__half2*)&ua.x), a1 = __half22float2(*(__half2*)&ua.y);
        float2 b0 = __half22float2(*(__half2*)&ub.x), b1f = __half22float2(*(__half2*)&ub.y);
        float2 c0 = __half22float2(*(__half2*)&uc.x), c1 = __half22float2(*(__half2*)&uc.y);
        float2 d0 = __half22float2(*(__half2*)&ud.x), d1 = __half22float2(*(__half2*)&ud.y);
        acc.x += (a0.x + b0.x) + (c0.x + d0.x);
        acc.y += (a0.y + b0.y) + (c0.y + d0.y);
        acc.z += (a1.x + b1f.x) + (c1.x + d1.x);
        acc.w += (a1.y + b1f.y) + (c1.y + d1.y);
    }
    for (; j < len; j++) {
        int r = __ldg(csr + start + j);
        uint2 ua = __ldg(&f2[(size_t)r * 32 + lane]);
        float2 a0 = __half22float2(*(__half2*)&ua.x);
        float2 a1 = __half22float2(*(__half2*)&ua.y);
        acc.x += a0.x; acc.y += a0.y; acc.z += a1.x; acc.w += a1.y;
    }
    if (RELU) {
        float w = dinv[node];
        float4 b = ((const float4*)b1)[lane];   // feats [lane*4, lane*4+4)
        float ox = fmaxf(fmaf(acc.x, w, b.x), 0.f) * w;
        float oy = fmaxf(fmaf(acc.y, w, b.y), 0.f) * w;
        float oz = fmaxf(fmaf(acc.z, w, b.z), 0.f) * w;
        float ow = fmaxf(fmaf(acc.w, w, b.w), 0.f) * w;
        __half2 p0 = __floats2half2_rn(ox, oy);
        __half2 p1 = __floats2half2_rn(oz, ow);
        uint2 o;
        o.x = *(unsigned*)&p0;
        o.y = *(unsigned*)&p1;
        ((uint2*)out)[(size_t)node * 32 + lane] = o;
    } else {
        ((float4*)out)[(size_t)node * 32 + lane] = acc;
    }
}

// ------- tiled fp32 GEMM, epilogue writes HALF: Ch = half((A @ B) * rowscale) -
template<int BM, int BN, int BK, int TM, int TN>
__global__ void sgemm_half_out_kernel(const float* __restrict__ A, const float* __restrict__ B,
                                      const float* __restrict__ rowscale,
                                      __half* __restrict__ Ch, int M, int N, int K) {
    constexpr int THREADS = (BM / TM) * (BN / TN);
    __shared__ float As[BK][BM + 4];
    __shared__ float Bs[BK][BN];
    const int tid  = threadIdx.x;
    const int brow = blockIdx.y * BM;
    const int bcol = blockIdx.x * BN;
    const int tr = (tid / (BN / TN)) * TM;
    const int tc = (tid % (BN / TN)) * TN;
    float acc[TM][TN] = {};

    constexpr int A_F4 = BM * BK / 4;
    constexpr int B_F4 = BK * BN / 4;

    for (int k0 = 0; k0 < K; k0 += BK) {
        #pragma unroll
        for (int i = tid; i < A_F4; i += THREADS) {
            int r  = i / (BK / 4);
            int kq = i % (BK / 4);
            float4 v = make_float4(0.f, 0.f, 0.f, 0.f);
            int gr = brow + r;
            if (gr < M) v = *(const float4*)(A + (size_t)gr * K + k0 + kq * 4);
            As[kq * 4 + 0][r] = v.x;
            As[kq * 4 + 1][r] = v.y;
            As[kq * 4 + 2][r] = v.z;
            As[kq * 4 + 3][r] = v.w;
        }
        #pragma unroll
        for (int i = tid; i < B_F4; i += THREADS) {
            int kk = i / (BN / 4);
            int c4 = i % (BN / 4);
            *(float4*)&Bs[kk][c4 * 4] =
                *(const float4*)(B + (size_t)(k0 + kk) * N + bcol + c4 * 4);
        }
        __syncthreads();
        #pragma unroll
        for (int kk = 0; kk < BK; kk++) {
            float ra[TM], rb[TN];
            #pragma unroll
            for (int i = 0; i < TM; i++) ra[i] = As[kk][tr + i];
            #pragma unroll
            for (int j = 0; j < TN; j++) rb[j] = Bs[kk][tc + j];
            #pragma unroll
            for (int i = 0; i < TM; i++)
                #pragma unroll
                for (int j = 0; j < TN; j++)
                    acc[i][j] = fmaf(ra[i], rb[j], acc[i][j]);
        }
        __syncthreads();
    }

    #pragma unroll
    for (int i = 0; i < TM; i++) {
        int gr = brow + tr + i;
        if (gr >= M) continue;
        float w = rowscale[gr];
        #pragma unroll
        for (int j = 0; j < TN; j += 4) {
            __half2 p0 = __floats2half2_rn(acc[i][j + 0] * w, acc[i][j + 1] * w);
            __half2 p1 = __floats2half2_rn(acc[i][j + 2] * w, acc[i][j + 3] * w);
            uint2 o;
            o.x = *(unsigned*)&p0;
            o.y = *(unsigned*)&p1;
            *(uint2*)(Ch + (size_t)gr * N + bcol + tc + j) = o;
        }
    }
}

// --------- fused tail GEMM: [mu | lv] = (A*rowscale) @ [Wmu | Wlv] + bias -----
template<int BM, int BK, int TM, int TN>
__global__ void tail_gemm_kernel(const float* __restrict__ A,
                                 const float* __restrict__ rowscale,
                                 const float* __restrict__ Wmu, const float* __restrict__ bmu,
                                 const float* __restrict__ Wlv, const float* __restrict__ blv,
                                 float* __restrict__ out, int M, int K) {
    constexpr int BN = 128;
    constexpr int THREADS = (BM / TM) * (BN / TN);
    __shared__ float As[BK][BM + 4];
    __shared__ float Bs[BK][BN];
    const int tid  = threadIdx.x;
    const int brow = blockIdx.y * BM;
    const int tr = (tid / (BN / TN)) * TM;
    const int tc = (tid % (BN / TN)) * TN;
    float acc[TM][TN] = {};

    constexpr int A_F4 = BM * BK / 4;
    constexpr int B_F4 = BK * BN / 4;

    for (int k0 = 0; k0 < K; k0 += BK) {
        #pragma unroll
        for (int i = tid; i < A_F4; i += THREADS) {
            int r  = i / (BK / 4);
            int kq = i % (BK / 4);
            float4 v = make_float4(0.f, 0.f, 0.f, 0.f);
            int gr = brow + r;
            if (gr < M) {
                v = *(const float4*)(A + (size_t)gr * K + k0 + kq * 4);
                float w = rowscale[gr];
                v.x *= w; v.y *= w; v.z *= w; v.w *= w;
            }
            As[kq * 4 + 0][r] = v.x;
            As[kq * 4 + 1][r] = v.y;
            As[kq * 4 + 2][r] = v.z;
            As[kq * 4 + 3][r] = v.w;
        }
        #pragma unroll
        for (int i = tid; i < B_F4; i += THREADS) {
            int kk = i / (BN / 4);
            int c4 = i % (BN / 4);          // c4<16 -> mu, else lv
            const float* src = (c4 < 16) ? (Wmu + (size_t)(k0 + kk) * 64 + c4 * 4)
                                         : (Wlv + (size_t)(k0 + kk) * 64 + (c4 - 16) * 4);
            *(float4*)&Bs[kk][c4 * 4] = *(const float4*)src;
        }
        __syncthreads();
        #pragma unroll
        for (int kk = 0; kk < BK; kk++) {
            float ra[TM], rb[TN];
            #pragma unroll
            for (int i = 0; i < TM; i++) ra[i] = As[kk][tr + i];
            #pragma unroll
            for (int j = 0; j < TN; j++) rb[j] = Bs[kk][tc + j];
            #pragma unroll
            for (int i = 0; i < TM; i++)
                #pragma unroll
                for (int j = 0; j < TN; j++)
                    acc[i][j] = fmaf(ra[i], rb[j], acc[i][j]);
        }
        __syncthreads();
    }

    #pragma unroll
    for (int i = 0; i < TM; i++) {
        int gr = brow + tr + i;
        if (gr >= M) continue;
        #pragma unroll
        for (int j = 0; j < TN; j += 4) {
            int col = tc + j;
            int lcol = (col < 64) ? col : col - 64;
            const float* bias = (col < 64) ? bmu : blv;
            float* base = (col < 64) ? out : out + (size_t)M * 64;
            float4 v;
            v.x = acc[i][j + 0] + bias[lcol + 0];
            v.y = acc[i][j + 1] + bias[lcol + 1];
            v.z = acc[i][j + 2] + bias[lcol + 2];
            v.w = acc[i][j + 3] + bias[lcol + 3];
            *(float4*)(base + (size_t)gr * 64 + lcol) = v;
        }
    }
}

// ---------------- launch ------------------------------------------------------
extern "C" void kernel_launch(void* const* d_in, const int* in_sizes, int n_in,
                              void* d_out, int out_size) {
    const float* X   = (const float*)d_in[0];
    const int*   ei  = (const int*)d_in[1];
    const float* W1  = (const float*)d_in[2];
    const float* b1  = (const float*)d_in[3];
    const float* Wmu = (const float*)d_in[4];
    const float* bmu = (const float*)d_in[5];
    const float* Wlv = (const float*)d_in[6];
    const float* blv = (const float*)d_in[7];
    const int Nn = in_sizes[0] / FIN;       // 100000
    const int E  = in_sizes[1] / 2;         // 1600000
    float* out = (float*)d_out;

    __half *T1h, *Hh;
    float *H, *dinv;
    int *deg, *row_start, *cur, *csr, *bsums, *boff;
    cudaGetSymbolAddress((void**)&T1h,      g_T1h);
    cudaGetSymbolAddress((void**)&Hh,       g_Hh);
    cudaGetSymbolAddress((void**)&H,        g_H);
    cudaGetSymbolAddress((void**)&dinv,     g_dinv);
    cudaGetSymbolAddress((void**)&deg,      g_deg);
    cudaGetSymbolAddress((void**)&row_start,g_rowstart);
    cudaGetSymbolAddress((void**)&cur,      g_cur);
    cudaGetSymbolAddress((void**)&csr,      g_csr);
    cudaGetSymbolAddress((void**)&bsums,    g_blocksums);
    cudaGetSymbolAddress((void**)&boff,     g_blockoff);

    const int nblk256 = (Nn + 255) / 256;   // 391

    // degrees + dinv
    zero_deg_kernel<<<nblk256, 256>>>(deg, Nn);
    deg_kernel<<<(E + 255) / 256, 256>>>(ei, E, Nn, deg);
    dinv_kernel<<<nblk256, 256>>>(deg, dinv, Nn);

    // CSR build
    scan1_kernel<<<nblk256, 256>>>(deg, Nn, row_start, bsums);
    scan2_kernel<<<1, 512>>>(bsums, nblk256, boff);
    scan3_kernel<<<nblk256, 256>>>(row_start, boff, Nn, cur);
    fill_kernel<<<(E + 255) / 256, 256>>>(ei, E, Nn, cur, csr);

    // T1h = half((X @ W1) * dinv[row])
    {
        dim3 grid(1, (Nn + 127) / 128);
        sgemm_half_out_kernel<128, 128, 32, 8, 8><<<grid, 256>>>(X, W1, dinv, T1h, Nn, F1, FIN);
    }

    // layer 1 aggregation + fused relu/bias/scale -> half Hs
    {
        int blocks = (Nn * 32 + 255) / 256;
        agg_half_kernel<true><<<blocks, 256>>>(row_start, deg, csr, T1h, dinv, b1, Hh, Nn);
    }

    // layer 2 aggregation (raw, fp32 out): AHraw -> H
    {
        int blocks = (Nn * 32 + 255) / 256;
        agg_half_kernel<false><<<blocks, 256>>>(row_start, deg, csr, Hh, dinv, b1, H, Nn);
    }

    // [mu | lv] = (AHraw * dinv[row]) @ [Wmu | Wlv] + bias
    {
        dim3 grid(1, (Nn + 127) / 128);
        tail_gemm_kernel<128, 32, 8, 8><<<grid, 256>>>(H, dinv, Wmu, bmu, Wlv, blv, out, Nn, F1);
    }
}

// round 16
// speedup vs baseline: 1.6266x; 1.1897x over previous
#include <cuda_runtime.h>
#include <cuda_fp16.h>
#include <cuda_bf16.h>
#include <mma.h>
#include <math.h>

using namespace nvcuda;

#define NMAX 100000
#define EMAX 1600000
#define F1   128   // hidden
#define FIN  256

// ---------------- scratch (static __device__ arrays) --------------------------
__device__ __half g_T1h[(size_t)NMAX * F1];  // half T1s = (X@W1)*dinv
__device__ __half g_Hh [(size_t)NMAX * F1];  // half Hs  = relu(...)*dinv
__device__ float  g_H  [(size_t)NMAX * F1];  // fp32 AHraw (tail GEMM input)
__device__ float  g_dinv[NMAX];
__device__ int    g_deg [NMAX];
__device__ int    g_rowstart[NMAX];
__device__ int    g_cur[NMAX];
__device__ int    g_csr[EMAX];
__device__ int    g_blocksums[512];
__device__ int    g_blockoff[512];

// ---------------- degree ------------------------------------------------------
__global__ void zero_deg_kernel(int* __restrict__ deg, int n) {
    int i = blockIdx.x * blockDim.x + threadIdx.x;
    if (i < n) deg[i] = 0;
}

__global__ void deg_kernel(const int* __restrict__ ei, int E, int Nn, int* __restrict__ deg) {
    int e = blockIdx.x * blockDim.x + threadIdx.x;
    if (e < E) {
        int c = ei[E + e];
        if ((unsigned)c < (unsigned)Nn) atomicAdd(&deg[c], 1);
    }
}

__global__ void dinv_kernel(const int* __restrict__ deg, float* __restrict__ dinv, int n) {
    int i = blockIdx.x * blockDim.x + threadIdx.x;
    if (i < n) dinv[i] = rsqrtf((float)(deg[i] + 1));
}

// ---------------- prefix-sum (3 kernels) for CSR row starts -------------------
__global__ void scan1_kernel(const int* __restrict__ deg, int n,
                             int* __restrict__ row_start, int* __restrict__ blockSums) {
    __shared__ int s[256];
    int tid = threadIdx.x;
    int i = blockIdx.x * 256 + tid;
    int v = (i < n) ? deg[i] : 0;
    s[tid] = v; __syncthreads();
    #pragma unroll
    for (int off = 1; off < 256; off <<= 1) {
        int t = (tid >= off) ? s[tid - off] : 0;
        __syncthreads();
        s[tid] += t;
        __syncthreads();
    }
    if (i < n) row_start[i] = s[tid] - v;
    if (tid == 255) blockSums[blockIdx.x] = s[255];
}

__global__ void scan2_kernel(const int* __restrict__ blockSums, int nb,
                             int* __restrict__ blockOff) {
    __shared__ int s[512];
    int tid = threadIdx.x;
    int v = (tid < nb) ? blockSums[tid] : 0;
    s[tid] = v; __syncthreads();
    #pragma unroll
    for (int off = 1; off < 512; off <<= 1) {
        int t = (tid >= off) ? s[tid - off] : 0;
        __syncthreads();
        s[tid] += t;
        __syncthreads();
    }
    if (tid < nb) blockOff[tid] = s[tid] - v;
}

__global__ void scan3_kernel(int* __restrict__ row_start, const int* __restrict__ blockOff,
                             int n, int* __restrict__ cur) {
    int i = blockIdx.x * 256 + threadIdx.x;
    if (i < n) {
        int rs = row_start[i] + blockOff[blockIdx.x];
        row_start[i] = rs;
        cur[i] = rs;
    }
}

__global__ void fill_kernel(const int* __restrict__ ei, int E, int Nn,
                            int* __restrict__ cur, int* __restrict__ csr) {
    int e = blockIdx.x * blockDim.x + threadIdx.x;
    if (e < E) {
        int r = ei[e];
        int c = ei[E + e];
        if ((unsigned)r < (unsigned)Nn && (unsigned)c < (unsigned)Nn) {
            int pos = atomicAdd(&cur[c], 1);
            csr[pos] = r;
        }
    }
}

// ---------------- CSR gather aggregation over HALF feature tables -------------
template<bool RELU>
__global__ void agg_half_kernel(const int* __restrict__ row_start,
                                const int* __restrict__ deg,
                                const int* __restrict__ csr,
                                const __half* __restrict__ feat,
                                const float* __restrict__ dinv,
                                const float* __restrict__ b1,
                                void* __restrict__ out, int Nn) {
    int node = (blockIdx.x * blockDim.x + threadIdx.x) >> 5;
    int lane = threadIdx.x & 31;
    if (node >= Nn) return;
    int start = row_start[node];
    int len   = deg[node];
    const uint2* f2 = (const uint2*)feat;
    uint2 u = __ldg(&f2[(size_t)node * 32 + lane]);
    float2 s0 = __half22float2(*(__half2*)&u.x);
    float2 s1 = __half22float2(*(__half2*)&u.y);
    float4 acc = make_float4(s0.x, s0.y, s1.x, s1.y);
    int j = 0;
    for (; j + 4 <= len; j += 4) {
        int r0 = __ldg(csr + start + j + 0);
        int r1 = __ldg(csr + start + j + 1);
        int r2 = __ldg(csr + start + j + 2);
        int r3 = __ldg(csr + start + j + 3);
        uint2 ua = __ldg(&f2[(size_t)r0 * 32 + lane]);
        uint2 ub = __ldg(&f2[(size_t)r1 * 32 + lane]);
        uint2 uc = __ldg(&f2[(size_t)r2 * 32 + lane]);
        uint2 ud = __ldg(&f2[(size_t)r3 * 32 + lane]);
        float2 a0 = __half22float2(*(__half2*)&ua.x), a1 = __half22float2(*(__half2*)&ua.y);
        float2 b0 = __half22float2(*(__half2*)&ub.x), b1f = __half22float2(*(__half2*)&ub.y);
        float2 c0 = __half22float2(*(__half2*)&uc.x), c1 = __half22float2(*(__half2*)&uc.y);
        float2 d0 = __half22float2(*(__half2*)&ud.x), d1 = __half22float2(*(__half2*)&ud.y);
        acc.x += (a0.x + b0.x) + (c0.x + d0.x);
        acc.y += (a0.y + b0.y) + (c0.y + d0.y);
        acc.z += (a1.x + b1f.x) + (c1.x + d1.x);
        acc.w += (a1.y + b1f.y) + (c1.y + d1.y);
    }
    for (; j < len; j++) {
        int r = __ldg(csr + start + j);
        uint2 ua = __ldg(&f2[(size_t)r * 32 + lane]);
        float2 a0 = __half22float2(*(__half2*)&ua.x);
        float2 a1 = __half22float2(*(__half2*)&ua.y);
        acc.x += a0.x; acc.y += a0.y; acc.z += a1.x; acc.w += a1.y;
    }
    if (RELU) {
        float w = dinv[node];
        float4 b = ((const float4*)b1)[lane];
        float ox = fmaxf(fmaf(acc.x, w, b.x), 0.f) * w;
        float oy = fmaxf(fmaf(acc.y, w, b.y), 0.f) * w;
        float oz = fmaxf(fmaf(acc.z, w, b.z), 0.f) * w;
        float ow = fmaxf(fmaf(acc.w, w, b.w), 0.f) * w;
        __half2 p0 = __floats2half2_rn(ox, oy);
        __half2 p1 = __floats2half2_rn(oz, ow);
        uint2 o;
        o.x = *(unsigned*)&p0;
        o.y = *(unsigned*)&p1;
        ((uint2*)out)[(size_t)node * 32 + lane] = o;
    } else {
        ((float4*)out)[(size_t)node * 32 + lane] = acc;
    }
}

// ---------------- split helper ------------------------------------------------
__device__ __forceinline__ void bf16_split(float x, __nv_bfloat16& hi, __nv_bfloat16& lo) {
    hi = __float2bfloat16(x);
    lo = __float2bfloat16(x - __bfloat162float(hi));
}

// ------- WMMA split-bf16 GEMM1: T1h = half((X[M,256] @ W1[256,128]) * dinv) ---
// block = 256 thr (8 warps, 2x4 warp grid of 32x32 tiles), BM=64, BN=128
__global__ void wmma_gemm1_kernel(const float* __restrict__ X, const float* __restrict__ W1,
                                  const float* __restrict__ dinv,
                                  __half* __restrict__ Ch, int M) {
    constexpr int BM = 64, BN = 128, KSTEP = 16, KTOT = FIN;
    __shared__ __nv_bfloat16 Ah[BM][24], Al[BM][24];
    __shared__ __nv_bfloat16 Bh[KSTEP][136], Bl[KSTEP][136];
    __shared__ float stag[8][32][32];
    const int tid = threadIdx.x;
    const int wid = tid >> 5, lane = tid & 31;
    const int wm = wid >> 2, wn = wid & 3;
    const int brow = blockIdx.x * BM;

    wmma::fragment<wmma::accumulator, 16, 16, 16, float> acc[2][2];
    #pragma unroll
    for (int m = 0; m < 2; m++)
        #pragma unroll
        for (int n = 0; n < 2; n++) wmma::fill_fragment(acc[m][n], 0.f);

    for (int k0 = 0; k0 < KTOT; k0 += KSTEP) {
        {   // A tile 64x16 (one float4 per thread)
            int row = tid >> 2, cg = tid & 3;
            int gr = brow + row;
            float4 v = make_float4(0.f, 0.f, 0.f, 0.f);
            if (gr < M) v = *(const float4*)(X + (size_t)gr * KTOT + k0 + cg * 4);
            float vv[4] = {v.x, v.y, v.z, v.w};
            #pragma unroll
            for (int i = 0; i < 4; i++)
                bf16_split(vv[i], Ah[row][cg * 4 + i], Al[row][cg * 4 + i]);
        }
        #pragma unroll
        for (int t = tid; t < 512; t += 256) {   // B tile 16x128
            int kk = t >> 5, c4 = t & 31;
            float4 v = *(const float4*)(W1 + (size_t)(k0 + kk) * BN + c4 * 4);
            float vv[4] = {v.x, v.y, v.z, v.w};
            #pragma unroll
            for (int i = 0; i < 4; i++)
                bf16_split(vv[i], Bh[kk][c4 * 4 + i], Bl[kk][c4 * 4 + i]);
        }
        __syncthreads();
        wmma::fragment<wmma::matrix_a, 16, 16, 16, __nv_bfloat16, wmma::row_major> a_hi[2], a_lo[2];
        wmma::fragment<wmma::matrix_b, 16, 16, 16, __nv_bfloat16, wmma::row_major> b_hi[2], b_lo[2];
        #pragma unroll
        for (int m = 0; m < 2; m++) {
            wmma::load_matrix_sync(a_hi[m], &Ah[wm * 32 + m * 16][0], 24);
            wmma::load_matrix_sync(a_lo[m], &Al[wm * 32 + m * 16][0], 24);
        }
        #pragma unroll
        for (int n = 0; n < 2; n++) {
            wmma::load_matrix_sync(b_hi[n], &Bh[0][wn * 32 + n * 16], 136);
            wmma::load_matrix_sync(b_lo[n], &Bl[0][wn * 32 + n * 16], 136);
        }
        #pragma unroll
        for (int m = 0; m < 2; m++)
            #pragma unroll
            for (int n = 0; n < 2; n++) {
                wmma::mma_sync(acc[m][n], a_hi[m], b_hi[n], acc[m][n]);
                wmma::mma_sync(acc[m][n], a_hi[m], b_lo[n], acc[m][n]);
                wmma::mma_sync(acc[m][n], a_lo[m], b_hi[n], acc[m][n]);
            }
        __syncthreads();
    }
    #pragma unroll
    for (int m = 0; m < 2; m++)
        #pragma unroll
        for (int n = 0; n < 2; n++)
            wmma::store_matrix_sync(&stag[wid][m * 16][n * 16], acc[m][n], 32, wmma::mem_row_major);
    __syncwarp();
    int gr = brow + wm * 32 + lane;
    if (gr < M) {
        float w = dinv[gr];
        __half* dst = Ch + (size_t)gr * BN + wn * 32;
        #pragma unroll
        for (int j = 0; j < 32; j += 8) {
            __half2 h0 = __floats2half2_rn(stag[wid][lane][j + 0] * w, stag[wid][lane][j + 1] * w);
            __half2 h1 = __floats2half2_rn(stag[wid][lane][j + 2] * w, stag[wid][lane][j + 3] * w);
            __half2 h2 = __floats2half2_rn(stag[wid][lane][j + 4] * w, stag[wid][lane][j + 5] * w);
            __half2 h3 = __floats2half2_rn(stag[wid][lane][j + 6] * w, stag[wid][lane][j + 7] * w);
            uint4 o = make_uint4(*(unsigned*)&h0, *(unsigned*)&h1, *(unsigned*)&h2, *(unsigned*)&h3);
            *(uint4*)(dst + j) = o;
        }
    }
}

// ------- WMMA split-bf16 tail: [mu|lv] = (H*dinv) @ [Wmu|Wlv] + bias ----------
__global__ void wmma_tail_kernel(const float* __restrict__ A, const float* __restrict__ dinv,
                                 const float* __restrict__ Wmu, const float* __restrict__ bmu,
                                 const float* __restrict__ Wlv, const float* __restrict__ blv,
                                 float* __restrict__ out, int M) {
    constexpr int BM = 64, BN = 128, KSTEP = 16, KTOT = F1;
    __shared__ __nv_bfloat16 Ah[BM][24], Al[BM][24];
    __shared__ __nv_bfloat16 Bh[KSTEP][136], Bl[KSTEP][136];
    __shared__ float stag[8][32][32];
    const int tid = threadIdx.x;
    const int wid = tid >> 5, lane = tid & 31;
    const int wm = wid >> 2, wn = wid & 3;
    const int brow = blockIdx.x * BM;

    wmma::fragment<wmma::accumulator, 16, 16, 16, float> acc[2][2];
    #pragma unroll
    for (int m = 0; m < 2; m++)
        #pragma unroll
        for (int n = 0; n < 2; n++) wmma::fill_fragment(acc[m][n], 0.f);

    for (int k0 = 0; k0 < KTOT; k0 += KSTEP) {
        {   // A tile 64x16, scaled by dinv[row]
            int row = tid >> 2, cg = tid & 3;
            int gr = brow + row;
            float4 v = make_float4(0.f, 0.f, 0.f, 0.f);
            if (gr < M) {
                v = *(const float4*)(A + (size_t)gr * KTOT + k0 + cg * 4);
                float w = dinv[gr];
                v.x *= w; v.y *= w; v.z *= w; v.w *= w;
            }
            float vv[4] = {v.x, v.y, v.z, v.w};
            #pragma unroll
            for (int i = 0; i < 4; i++)
                bf16_split(vv[i], Ah[row][cg * 4 + i], Al[row][cg * 4 + i]);
        }
        #pragma unroll
        for (int t = tid; t < 512; t += 256) {   // B tile 16x128 = [Wmu | Wlv]
            int kk = t >> 5, c4 = t & 31;
            const float* src = (c4 < 16) ? (Wmu + (size_t)(k0 + kk) * 64 + c4 * 4)
                                         : (Wlv + (size_t)(k0 + kk) * 64 + (c4 - 16) * 4);
            float4 v = *(const float4*)src;
            float vv[4] = {v.x, v.y, v.z, v.w};
            #pragma unroll
            for (int i = 0; i < 4; i++)
                bf16_split(vv[i], Bh[kk][c4 * 4 + i], Bl[kk][c4 * 4 + i]);
        }
        __syncthreads();
        wmma::fragment<wmma::matrix_a, 16, 16, 16, __nv_bfloat16, wmma::row_major> a_hi[2], a_lo[2];
        wmma::fragment<wmma::matrix_b, 16, 16, 16, __nv_bfloat16, wmma::row_major> b_hi[2], b_lo[2];
        #pragma unroll
        for (int m = 0; m < 2; m++) {
            wmma::load_matrix_sync(a_hi[m], &Ah[wm * 32 + m * 16][0], 24);
            wmma::load_matrix_sync(a_lo[m], &Al[wm * 32 + m * 16][0], 24);
        }
        #pragma unroll
        for (int n = 0; n < 2; n++) {
            wmma::load_matrix_sync(b_hi[n], &Bh[0][wn * 32 + n * 16], 136);
            wmma::load_matrix_sync(b_lo[n], &Bl[0][wn * 32 + n * 16], 136);
        }
        #pragma unroll
        for (int m = 0; m < 2; m++)
            #pragma unroll
            for (int n = 0; n < 2; n++) {
                wmma::mma_sync(acc[m][n], a_hi[m], b_hi[n], acc[m][n]);
                wmma::mma_sync(acc[m][n], a_hi[m], b_lo[n], acc[m][n]);
                wmma::mma_sync(acc[m][n], a_lo[m], b_hi[n], acc[m][n]);
            }
        __syncthreads();
    }
    #pragma unroll
    for (int m = 0; m < 2; m++)
        #pragma unroll
        for (int n = 0; n < 2; n++)
            wmma::store_matrix_sync(&stag[wid][m * 16][n * 16], acc[m][n], 32, wmma::mem_row_major);
    __syncwarp();
    int gr = brow + wm * 32 + lane;
    if (gr < M) {
        // wn 0,1 -> mu (cols 0..63); wn 2,3 -> lv (cols 0..63 of lv)
        const float* bias = (wn < 2) ? bmu : blv;
        float* base = (wn < 2) ? out : out + (size_t)M * 64;
        int lcol = (wn & 1) * 32;
        float* dst = base + (size_t)gr * 64 + lcol;
        #pragma unroll
        for (int j = 0; j < 32; j += 4) {
            float4 v;
            v.x = stag[wid][lane][j + 0] + bias[lcol + j + 0];
            v.y = stag[wid][lane][j + 1] + bias[lcol + j + 1];
            v.z = stag[wid][lane][j + 2] + bias[lcol + j + 2];
            v.w = stag[wid][lane][j + 3] + bias[lcol + j + 3];
            *(float4*)(dst + j) = v;
        }
    }
}

// ---------------- launch ------------------------------------------------------
extern "C" void kernel_launch(void* const* d_in, const int* in_sizes, int n_in,
                              void* d_out, int out_size) {
    const float* X   = (const float*)d_in[0];
    const int*   ei  = (const int*)d_in[1];
    const float* W1  = (const float*)d_in[2];
    const float* b1  = (const float*)d_in[3];
    const float* Wmu = (const float*)d_in[4];
    const float* bmu = (const float*)d_in[5];
    const float* Wlv = (const float*)d_in[6];
    const float* blv = (const float*)d_in[7];
    const int Nn = in_sizes[0] / FIN;       // 100000
    const int E  = in_sizes[1] / 2;         // 1600000
    float* out = (float*)d_out;

    __half *T1h, *Hh;
    float *H, *dinv;
    int *deg, *row_start, *cur, *csr, *bsums, *boff;
    cudaGetSymbolAddress((void**)&T1h,      g_T1h);
    cudaGetSymbolAddress((void**)&Hh,       g_Hh);
    cudaGetSymbolAddress((void**)&H,        g_H);
    cudaGetSymbolAddress((void**)&dinv,     g_dinv);
    cudaGetSymbolAddress((void**)&deg,      g_deg);
    cudaGetSymbolAddress((void**)&row_start,g_rowstart);
    cudaGetSymbolAddress((void**)&cur,      g_cur);
    cudaGetSymbolAddress((void**)&csr,      g_csr);
    cudaGetSymbolAddress((void**)&bsums,    g_blocksums);
    cudaGetSymbolAddress((void**)&boff,     g_blockoff);

    const int nblk256 = (Nn + 255) / 256;   // 391

    // degrees + dinv
    zero_deg_kernel<<<nblk256, 256>>>(deg, Nn);
    deg_kernel<<<(E + 255) / 256, 256>>>(ei, E, Nn, deg);
    dinv_kernel<<<nblk256, 256>>>(deg, dinv, Nn);

    // CSR build
    scan1_kernel<<<nblk256, 256>>>(deg, Nn, row_start, bsums);
    scan2_kernel<<<1, 512>>>(bsums, nblk256, boff);
    scan3_kernel<<<nblk256, 256>>>(row_start, boff, Nn, cur);
    fill_kernel<<<(E + 255) / 256, 256>>>(ei, E, Nn, cur, csr);

    // T1h = half((X @ W1) * dinv[row])  -- tensor-core split-bf16
    wmma_gemm1_kernel<<<(Nn + 63) / 64, 256>>>(X, W1, dinv, T1h, Nn);

    // layer 1 aggregation + fused relu/bias/scale -> half Hs
    {
        int blocks = (Nn * 32 + 255) / 256;
        agg_half_kernel<true><<<blocks, 256>>>(row_start, deg, csr, T1h, dinv, b1, Hh, Nn);
    }

    // layer 2 aggregation (raw, fp32 out): AHraw -> H
    {
        int blocks = (Nn * 32 + 255) / 256;
        agg_half_kernel<false><<<blocks, 256>>>(row_start, deg, csr, Hh, dinv, b1, H, Nn);
    }

    // [mu | lv] = (AHraw * dinv[row]) @ [Wmu | Wlv] + bias  -- tensor-core
    wmma_tail_kernel<<<(Nn + 63) / 64, 256>>>(H, dinv, Wmu, bmu, Wlv, blv, out, Nn);
}